// round 11
// baseline (speedup 1.0000x reference)
#include <cuda_runtime.h>
#include <cstdint>

typedef unsigned long long u64;

#define E_CNT 100000
#define NDST  10000
#define OUTC  2048

// ---------------- small device scratch (CSR only) ----------------
__device__ int g_counts[NDST];
__device__ int g_cursor[NDST];
__device__ int g_eid   [E_CNT];

// ---------------- prologue kernels ----------------
__global__ void zero_cnt_k() {
    int i = blockIdx.x * blockDim.x + threadIdx.x;
    if (i < NDST) g_counts[i] = 0;
}
__global__ void hist_k(const int* __restrict__ dst) {
    int e = blockIdx.x * blockDim.x + threadIdx.x;
    if (e < E_CNT) atomicAdd(&g_counts[dst[e]], 1);
}
__global__ void scan_k() {
    __shared__ int ss[1024];
    const int tid = threadIdx.x;
    const int CH = 10;
    int base = tid * CH, loc[CH], s = 0;
#pragma unroll
    for (int i = 0; i < CH; i++) {
        int idx = base + i;
        int v = (idx < NDST) ? g_counts[idx] : 0;
        loc[i] = s; s += v;
    }
    ss[tid] = s; __syncthreads();
    for (int off = 1; off < 1024; off <<= 1) {
        int v = 0;
        if (tid >= off) v = ss[tid - off];
        __syncthreads();
        if (tid >= off) ss[tid] += v;
        __syncthreads();
    }
    int excl = (tid == 0) ? 0 : ss[tid - 1];
#pragma unroll
    for (int i = 0; i < CH; i++) {
        int idx = base + i;
        if (idx < NDST) g_cursor[idx] = excl + loc[i];
    }
}
__global__ void fill_k(const int* __restrict__ dst) {
    int e = blockIdx.x * blockDim.x + threadIdx.x;
    if (e < E_CNT) {
        int p = atomicAdd(&g_cursor[dst[e]], 1);
        g_eid[p] = e;
    }
}
__global__ void zero_out_k(float4* __restrict__ out, int n4) {
    int i = blockIdx.x * blockDim.x + threadIdx.x;
    if (i < n4) out[i] = make_float4(0.f, 0.f, 0.f, 0.f);
}

// ---------------- packed fp32x2 helpers ----------------
__device__ __forceinline__ void ffma2(u64& d, u64 a, u64 b) {
    asm("fma.rn.f32x2 %0, %1, %2, %0;" : "+l"(d) : "l"(a), "l"(b));
}
__device__ __forceinline__ u64 pack2(float x) {
    u64 r; asm("mov.b64 %0, {%1, %1};" : "=l"(r) : "f"(x)); return r;
}
__device__ __forceinline__ u64 packf2(float lo, float hi) {
    u64 r; asm("mov.b64 %0, {%1, %2};" : "=l"(r) : "f"(lo), "f"(hi)); return r;
}
__device__ __forceinline__ float2 unpack2(u64 v) {
    float2 f; asm("mov.b64 {%0, %1}, %2;" : "=f"(f.x), "=f"(f.y) : "l"(v)); return f;
}
__device__ __forceinline__ float silu_f(float x) {
    return x / (1.f + __expf(-x));
}

// ---------------- smem layout (float offsets) ----------------
// Hst [128][68] | Ws [64][128] (EMBt [64][68] aliases) |
// W1s [64][128] (TPW [64][128] aliases) | SHs [64][16] | ints
#define F_HST  0            // 8704 floats
#define F_WS   8704         // 8192 floats (EMBt aliases: 4352)
#define F_W1S  16896        // 8192 floats (TPW aliases)
#define F_SHS  25088        // 1024 floats
#define F_END  26112
#define SMEM_BYTES ((F_END + 192) * 4)

// ---------------- fused kernel: FFMA2 MLP + TP + segment scatter -----------
__global__ __launch_bounds__(256, 2) void fused_k(
    const float* __restrict__ src_features,
    const float* __restrict__ edge_sh,
    const float* __restrict__ edge_emb,
    const float* __restrict__ W1,
    const float* __restrict__ W2,
    const int*   __restrict__ src,
    const int*   __restrict__ dst,
    float*       __restrict__ out)
{
    extern __shared__ float sm[];
    float* Hst  = sm + F_HST;    // [k=128][row 64+4pad]
    float* Ws   = sm + F_WS;     // [k=64][n 128]
    float* EMBt = Ws;            // [k=64][row 64+4pad] alias
    float* W1s  = sm + F_W1S;    // [k=64][n 128]
    float* TPW  = W1s;           // [row 64][c 128] alias
    float* SHs  = sm + F_SHS;    // [row 64][16]
    int*   Es   = (int*)(sm + F_END);
    int*   Ss   = Es + 64;
    int*   Ds   = Ss + 64;

    const int tid = threadIdx.x;
    const int tr  = tid >> 5;     // warp id 0..7 -> rows tr*8 .. tr*8+7
    const int tc  = tid & 31;     // lane -> cols tc*4 .. tc*4+3
    const int r0  = tr * 8;
    const int c0  = tc * 4;

    // ---- stage edge metadata (pads replicate last edge; SH pads -> 0) ----
    const int pos0 = blockIdx.x * 64;
    const int nE   = (E_CNT - pos0 < 64) ? (E_CNT - pos0) : 64;
    if (tid < 64) {
        int sl = (tid < nE) ? tid : (nE - 1);
        int e  = g_eid[pos0 + sl];
        Es[tid] = e; Ss[tid] = src[e]; Ds[tid] = dst[e];
    }
    __syncthreads();

    // ---- stage EMBt (transposed, slot-major => conflict-free STS) ----
#pragma unroll
    for (int it = 0; it < 4; it++) {
        int li = it * 256 + tid;
        int slot = li & 63, fq = li >> 6;       // fq 0..15
        float4 v = *(const float4*)&edge_emb[(size_t)Es[slot] * 64 + fq * 4];
        EMBt[(fq * 4 + 0) * 68 + slot] = v.x;
        EMBt[(fq * 4 + 1) * 68 + slot] = v.y;
        EMBt[(fq * 4 + 2) * 68 + slot] = v.z;
        EMBt[(fq * 4 + 3) * 68 + slot] = v.w;
    }
#pragma unroll
    for (int it = 0; it < 8; it++) {           // W1s[k][n] = W1[k][n]/8
        int li = tid + it * 256;
        int k = li >> 5, f = li & 31;
        float4 v = *(const float4*)&W1[(size_t)k * 128 + f * 4];
        v.x *= 0.125f; v.y *= 0.125f; v.z *= 0.125f; v.w *= 0.125f;
        *(float4*)&W1s[k * 128 + f * 4] = v;
    }
    {                                          // SHs: 64 x 4 float4 (zero pads)
        int slot = tid >> 2, j = tid & 3;
        float4 v = make_float4(0.f, 0.f, 0.f, 0.f);
        if (slot < nE)
            v = *(const float4*)&edge_sh[(size_t)Es[slot] * 16 + j * 4];
        *(float4*)&SHs[slot * 16 + j * 4] = v;
    }
    __syncthreads();

    // ---- GEMM1: Hst = silu(EMB @ W1s)^T, 64x128x64, FFMA2 ----
    {
        u64 acc[4][4];   // [row-pair p][col j]
#pragma unroll
        for (int p = 0; p < 4; p++)
#pragma unroll
            for (int j = 0; j < 4; j++) acc[p][j] = 0ull;

#pragma unroll 8
        for (int kk = 0; kk < 64; kk++) {
            float4 rb = *(const float4*)&W1s[kk * 128 + c0];
            u64 bb0 = pack2(rb.x), bb1 = pack2(rb.y);
            u64 bb2 = pack2(rb.z), bb3 = pack2(rb.w);
            ulonglong2 aA = *(const ulonglong2*)&EMBt[kk * 68 + r0];      // pairs 0,1
            ulonglong2 aB = *(const ulonglong2*)&EMBt[kk * 68 + r0 + 4];  // pairs 2,3
            ffma2(acc[0][0], aA.x, bb0); ffma2(acc[0][1], aA.x, bb1);
            ffma2(acc[0][2], aA.x, bb2); ffma2(acc[0][3], aA.x, bb3);
            ffma2(acc[1][0], aA.y, bb0); ffma2(acc[1][1], aA.y, bb1);
            ffma2(acc[1][2], aA.y, bb2); ffma2(acc[1][3], aA.y, bb3);
            ffma2(acc[2][0], aB.x, bb0); ffma2(acc[2][1], aB.x, bb1);
            ffma2(acc[2][2], aB.x, bb2); ffma2(acc[2][3], aB.x, bb3);
            ffma2(acc[3][0], aB.y, bb0); ffma2(acc[3][1], aB.y, bb1);
            ffma2(acc[3][2], aB.y, bb2); ffma2(acc[3][3], aB.y, bb3);
        }
        // epilogue: silu -> Hst[c][row] (pair store)
#pragma unroll
        for (int p = 0; p < 4; p++)
#pragma unroll
            for (int j = 0; j < 4; j++) {
                float2 v = unpack2(acc[p][j]);
                v.x = silu_f(v.x); v.y = silu_f(v.y);
                *(u64*)&Hst[(c0 + j) * 68 + r0 + 2 * p] = packf2(v.x, v.y);
            }
    }
    __syncthreads();   // Hst ready; EMBt(Ws) and W1s(TPW) free

    // ---- per-l: GEMM2 (FFMA2) + fold x + run-length segment scatter ----
    const float w2s = 0.08838834764831845f;    // 1/sqrt(128)

    for (int l = 0; l < 4; l++) {
        u64 acc[4][4];
#pragma unroll
        for (int p = 0; p < 4; p++)
#pragma unroll
            for (int j = 0; j < 4; j++) acc[p][j] = 0ull;

        for (int k0 = 0; k0 < 128; k0 += 64) {
            if (k0) __syncthreads();           // Ws reuse guard within l
            // stage Ws[k][n] = W2[k0+k][l*128+n] * w2s
#pragma unroll
            for (int it = 0; it < 8; it++) {
                int li = tid + it * 256;
                int k = li >> 5, f = li & 31;
                float4 v = *(const float4*)&W2[(size_t)(k0 + k) * 512 + l * 128 + f * 4];
                v.x *= w2s; v.y *= w2s; v.z *= w2s; v.w *= w2s;
                *(float4*)&Ws[k * 128 + f * 4] = v;
            }
            __syncthreads();

#pragma unroll 8
            for (int kk = 0; kk < 64; kk++) {
                float4 rb = *(const float4*)&Ws[kk * 128 + c0];
                u64 bb0 = pack2(rb.x), bb1 = pack2(rb.y);
                u64 bb2 = pack2(rb.z), bb3 = pack2(rb.w);
                ulonglong2 aA = *(const ulonglong2*)&Hst[(k0 + kk) * 68 + r0];
                ulonglong2 aB = *(const ulonglong2*)&Hst[(k0 + kk) * 68 + r0 + 4];
                ffma2(acc[0][0], aA.x, bb0); ffma2(acc[0][1], aA.x, bb1);
                ffma2(acc[0][2], aA.x, bb2); ffma2(acc[0][3], aA.x, bb3);
                ffma2(acc[1][0], aA.y, bb0); ffma2(acc[1][1], aA.y, bb1);
                ffma2(acc[1][2], aA.y, bb2); ffma2(acc[1][3], aA.y, bb3);
                ffma2(acc[2][0], aB.x, bb0); ffma2(acc[2][1], aB.x, bb1);
                ffma2(acc[2][2], aB.x, bb2); ffma2(acc[2][3], aB.x, bb3);
                ffma2(acc[3][0], aB.y, bb0); ffma2(acc[3][1], aB.y, bb1);
                ffma2(acc[3][2], aB.y, bb2); ffma2(acc[3][3], aB.y, bb3);
            }
        }
        __syncthreads();   // Ws reads + previous TPW use complete

        // fold: TPW[row][c] = acc * x_src[src[row]][c]
#pragma unroll
        for (int p = 0; p < 4; p++) {
            int rA = r0 + 2 * p, rB = rA + 1;
            float4 xA = *(const float4*)&src_features[(size_t)Ss[rA] * 128 + c0];
            float4 xB = *(const float4*)&src_features[(size_t)Ss[rB] * 128 + c0];
            float2 q0 = unpack2(acc[p][0]), q1 = unpack2(acc[p][1]);
            float2 q2 = unpack2(acc[p][2]), q3 = unpack2(acc[p][3]);
            *(float4*)&TPW[rA * 128 + c0] =
                make_float4(q0.x * xA.x, q1.x * xA.y, q2.x * xA.z, q3.x * xA.w);
            *(float4*)&TPW[rB * 128 + c0] =
                make_float4(q0.y * xB.x, q1.y * xB.y, q2.y * xB.z, q3.y * xB.w);
        }
        __syncthreads();

        // scatter: run-length reduce over 64 dst-sorted edges.
        // Interior runs are COMPLETE for their dst (CSR-sorted) -> plain STG.
        // Only the first run (may continue from prev tile) and the final run
        // (may continue into next tile) need atomics.
        {
            const int d    = 2 * l + 1;
            const int soff = l * l;
            const int ob   = (l == 0) ? 0 : (l == 1) ? 128 : (l == 2) ? 512 : 1152;
            const int ncol = 128 * d;
            for (int q = tid; q < ncol; q += 256) {
                const int c = q / d;
                const int s = q - c * d;
                float a = 0.f;
                int  cur    = Ds[0];
                bool bstart = true;
#pragma unroll 8
                for (int e = 0; e < 64; e++) {
                    int dn = Ds[e];
                    if (dn != cur) {
                        float* p = &out[(size_t)cur * OUTC + ob + q];
                        if (bstart) atomicAdd(p, a); else *p = a;
                        a = 0.f; cur = dn; bstart = false;
                    }
                    a += TPW[e * 128 + c] * SHs[e * 16 + soff + s];
                }
                atomicAdd(&out[(size_t)cur * OUTC + ob + q], a);
            }
        }
        __syncthreads();
    }
}

// ---------------- launch ----------------
extern "C" void kernel_launch(void* const* d_in, const int* in_sizes, int n_in,
                              void* d_out, int out_size)
{
    const float* src_features = (const float*)d_in[0];
    const float* edge_sh      = (const float*)d_in[1];
    const float* edge_emb     = (const float*)d_in[2];
    const float* W1           = (const float*)d_in[3];
    const float* W2           = (const float*)d_in[4];
    const int*   src          = (const int*)d_in[5];
    const int*   dst          = (const int*)d_in[6];
    float*       out          = (float*)d_out;
    (void)in_sizes; (void)n_in; (void)out_size;

    static bool attr_done = false;
    if (!attr_done) {
        cudaFuncSetAttribute(fused_k, cudaFuncAttributeMaxDynamicSharedMemorySize,
                             SMEM_BYTES);
        attr_done = true;
    }

    // CSR build
    zero_cnt_k<<<(NDST + 255) / 256, 256>>>();
    hist_k<<<(E_CNT + 255) / 256, 256>>>(dst);
    scan_k<<<1, 1024>>>();
    fill_k<<<(E_CNT + 255) / 256, 256>>>(dst);

    // zero output (STG-interior + atomic-boundary accumulation target)
    const int n4 = NDST * OUTC / 4;
    zero_out_k<<<(n4 + 255) / 256, 256>>>((float4*)out, n4);

    // fused FFMA2 MLP + TP + scatter (64 edges/block, 2 CTAs/SM)
    const int nblk = (E_CNT + 63) / 64;
    fused_k<<<nblk, 256, SMEM_BYTES>>>(src_features, edge_sh, edge_emb,
                                       W1, W2, src, dst, out);
}

// round 12
// speedup vs baseline: 1.5910x; 1.5910x over previous
#include <cuda_runtime.h>
#include <cstdint>

typedef unsigned long long u64;

#define E_CNT 100000
#define NDST  10000
#define OUTC  2048

// ---------------- small device scratch (CSR only) ----------------
__device__ int g_counts[NDST];
__device__ int g_cursor[NDST];
__device__ int g_eid   [E_CNT];

// ---------------- prologue kernels ----------------
__global__ void zero_cnt_k() {
    int i = blockIdx.x * blockDim.x + threadIdx.x;
    if (i < NDST) g_counts[i] = 0;
}
__global__ void hist_k(const int* __restrict__ dst) {
    int e = blockIdx.x * blockDim.x + threadIdx.x;
    if (e < E_CNT) atomicAdd(&g_counts[dst[e]], 1);
}
__global__ void scan_k() {
    __shared__ int ss[1024];
    const int tid = threadIdx.x;
    const int CH = 10;
    int base = tid * CH, loc[CH], s = 0;
#pragma unroll
    for (int i = 0; i < CH; i++) {
        int idx = base + i;
        int v = (idx < NDST) ? g_counts[idx] : 0;
        loc[i] = s; s += v;
    }
    ss[tid] = s; __syncthreads();
    for (int off = 1; off < 1024; off <<= 1) {
        int v = 0;
        if (tid >= off) v = ss[tid - off];
        __syncthreads();
        if (tid >= off) ss[tid] += v;
        __syncthreads();
    }
    int excl = (tid == 0) ? 0 : ss[tid - 1];
#pragma unroll
    for (int i = 0; i < CH; i++) {
        int idx = base + i;
        if (idx < NDST) g_cursor[idx] = excl + loc[i];
    }
}
__global__ void fill_k(const int* __restrict__ dst) {
    int e = blockIdx.x * blockDim.x + threadIdx.x;
    if (e < E_CNT) {
        int p = atomicAdd(&g_cursor[dst[e]], 1);
        g_eid[p] = e;
    }
}
__global__ void zero_out_k(float4* __restrict__ out, int n4) {
    int i = blockIdx.x * blockDim.x + threadIdx.x;
    if (i < n4) out[i] = make_float4(0.f, 0.f, 0.f, 0.f);
}

// ---------------- packed fp32x2 helpers ----------------
__device__ __forceinline__ void ffma2(u64& d, u64 a, u64 b) {
    asm("fma.rn.f32x2 %0, %1, %2, %0;" : "+l"(d) : "l"(a), "l"(b));
}
__device__ __forceinline__ u64 pack2(float x) {
    u64 r; asm("mov.b64 %0, {%1, %1};" : "=l"(r) : "f"(x)); return r;
}
__device__ __forceinline__ u64 packf2(float lo, float hi) {
    u64 r; asm("mov.b64 %0, {%1, %2};" : "=l"(r) : "f"(lo), "f"(hi)); return r;
}
__device__ __forceinline__ float2 unpack2(u64 v) {
    float2 f; asm("mov.b64 {%0, %1}, %2;" : "=f"(f.x), "=f"(f.y) : "l"(v)); return f;
}
__device__ __forceinline__ float silu_f(float x) {
    return x / (1.f + __expf(-x));
}

// ---------------- smem layout (float offsets) ----------------
// Hst [128][68] | Ws [64][128] (EMBt [64][68] aliases) |
// W1s [64][128] (TPW [64][128] aliases) | SHs [64][16] | ints
#define F_HST  0            // 8704 floats
#define F_WS   8704         // 8192 floats (EMBt aliases: 4352)
#define F_W1S  16896        // 8192 floats (TPW aliases)
#define F_SHS  25088        // 1024 floats
#define F_END  26112
#define SMEM_BYTES ((F_END + 192) * 4)

// ---------------- fused kernel: FFMA2 MLP + TP + segment scatter -----------
__global__ __launch_bounds__(256, 2) void fused_k(
    const float* __restrict__ src_features,
    const float* __restrict__ edge_sh,
    const float* __restrict__ edge_emb,
    const float* __restrict__ W1,
    const float* __restrict__ W2,
    const int*   __restrict__ src,
    const int*   __restrict__ dst,
    float*       __restrict__ out)
{
    extern __shared__ float sm[];
    float* Hst  = sm + F_HST;    // [k=128][row 64+4pad]
    float* Ws   = sm + F_WS;     // [k=64][n 128]
    float* EMBt = Ws;            // [k=64][row 64+4pad] alias
    float* W1s  = sm + F_W1S;    // [k=64][n 128]
    float* TPW  = W1s;           // [row 64][c 128] alias
    float* SHs  = sm + F_SHS;    // [row 64][16]
    int*   Es   = (int*)(sm + F_END);
    int*   Ss   = Es + 64;
    int*   Ds   = Ss + 64;

    const int tid = threadIdx.x;
    const int tr  = tid >> 5;     // warp id 0..7 -> rows tr*8 .. tr*8+7
    const int tc  = tid & 31;     // lane -> cols tc*4 .. tc*4+3
    const int r0  = tr * 8;
    const int c0  = tc * 4;

    // ---- stage edge metadata (pads replicate last edge; SH pads -> 0) ----
    const int pos0 = blockIdx.x * 64;
    const int nE   = (E_CNT - pos0 < 64) ? (E_CNT - pos0) : 64;
    if (tid < 64) {
        int sl = (tid < nE) ? tid : (nE - 1);
        int e  = g_eid[pos0 + sl];
        Es[tid] = e; Ss[tid] = src[e]; Ds[tid] = dst[e];
    }
    __syncthreads();

    // ---- stage EMBt (transposed, slot-major => conflict-free STS) ----
#pragma unroll
    for (int it = 0; it < 4; it++) {
        int li = it * 256 + tid;
        int slot = li & 63, fq = li >> 6;       // fq 0..15
        float4 v = *(const float4*)&edge_emb[(size_t)Es[slot] * 64 + fq * 4];
        EMBt[(fq * 4 + 0) * 68 + slot] = v.x;
        EMBt[(fq * 4 + 1) * 68 + slot] = v.y;
        EMBt[(fq * 4 + 2) * 68 + slot] = v.z;
        EMBt[(fq * 4 + 3) * 68 + slot] = v.w;
    }
#pragma unroll
    for (int it = 0; it < 8; it++) {           // W1s[k][n] = W1[k][n]/8
        int li = tid + it * 256;
        int k = li >> 5, f = li & 31;
        float4 v = *(const float4*)&W1[(size_t)k * 128 + f * 4];
        v.x *= 0.125f; v.y *= 0.125f; v.z *= 0.125f; v.w *= 0.125f;
        *(float4*)&W1s[k * 128 + f * 4] = v;
    }
    {                                          // SHs: 64 x 4 float4 (zero pads)
        int slot = tid >> 2, j = tid & 3;
        float4 v = make_float4(0.f, 0.f, 0.f, 0.f);
        if (slot < nE)
            v = *(const float4*)&edge_sh[(size_t)Es[slot] * 16 + j * 4];
        *(float4*)&SHs[slot * 16 + j * 4] = v;
    }
    __syncthreads();

    // ---- GEMM1: Hst = silu(EMB @ W1s)^T, 64x128x64, FFMA2 ----
    {
        u64 acc[4][4];   // [row-pair p][col j]: {row r0+2p, row r0+2p+1}
#pragma unroll
        for (int p = 0; p < 4; p++)
#pragma unroll
            for (int j = 0; j < 4; j++) acc[p][j] = 0ull;

#pragma unroll 8
        for (int kk = 0; kk < 64; kk++) {
            float4 rb = *(const float4*)&W1s[kk * 128 + c0];
            u64 bb0 = pack2(rb.x), bb1 = pack2(rb.y);
            u64 bb2 = pack2(rb.z), bb3 = pack2(rb.w);
#pragma unroll
            for (int p = 0; p < 4; p++) {
                u64 ap = *(const u64*)&EMBt[kk * 68 + r0 + 2 * p];  // pair broadcast
                ffma2(acc[p][0], ap, bb0); ffma2(acc[p][1], ap, bb1);
                ffma2(acc[p][2], ap, bb2); ffma2(acc[p][3], ap, bb3);
            }
        }
        // epilogue: silu -> Hst[c][row] (pair store)
#pragma unroll
        for (int p = 0; p < 4; p++)
#pragma unroll
            for (int j = 0; j < 4; j++) {
                float2 v = unpack2(acc[p][j]);
                v.x = silu_f(v.x); v.y = silu_f(v.y);
                *(u64*)&Hst[(c0 + j) * 68 + r0 + 2 * p] = packf2(v.x, v.y);
            }
    }
    __syncthreads();   // Hst ready; EMBt(Ws) and W1s(TPW) free

    // ---- per-l: GEMM2 (FFMA2) + fold x + run-length segment scatter ----
    const float w2s = 0.08838834764831845f;    // 1/sqrt(128)

    for (int l = 0; l < 4; l++) {
        u64 acc[4][4];
#pragma unroll
        for (int p = 0; p < 4; p++)
#pragma unroll
            for (int j = 0; j < 4; j++) acc[p][j] = 0ull;

        for (int k0 = 0; k0 < 128; k0 += 64) {
            if (k0) __syncthreads();           // Ws reuse guard within l
            // stage Ws[k][n] = W2[k0+k][l*128+n] * w2s
#pragma unroll
            for (int it = 0; it < 8; it++) {
                int li = tid + it * 256;
                int k = li >> 5, f = li & 31;
                float4 v = *(const float4*)&W2[(size_t)(k0 + k) * 512 + l * 128 + f * 4];
                v.x *= w2s; v.y *= w2s; v.z *= w2s; v.w *= w2s;
                *(float4*)&Ws[k * 128 + f * 4] = v;
            }
            __syncthreads();

#pragma unroll 8
            for (int kk = 0; kk < 64; kk++) {
                float4 rb = *(const float4*)&Ws[kk * 128 + c0];
                u64 bb0 = pack2(rb.x), bb1 = pack2(rb.y);
                u64 bb2 = pack2(rb.z), bb3 = pack2(rb.w);
#pragma unroll
                for (int p = 0; p < 4; p++) {
                    u64 ap = *(const u64*)&Hst[(k0 + kk) * 68 + r0 + 2 * p];
                    ffma2(acc[p][0], ap, bb0); ffma2(acc[p][1], ap, bb1);
                    ffma2(acc[p][2], ap, bb2); ffma2(acc[p][3], ap, bb3);
                }
            }
        }
        __syncthreads();   // Ws reads + previous TPW use complete

        // fold: TPW[row][c] = acc * x_src[src[row]][c]
#pragma unroll
        for (int p = 0; p < 4; p++) {
            int rA = r0 + 2 * p, rB = rA + 1;
            float4 xA = *(const float4*)&src_features[(size_t)Ss[rA] * 128 + c0];
            float4 xB = *(const float4*)&src_features[(size_t)Ss[rB] * 128 + c0];
            float2 q0 = unpack2(acc[p][0]), q1 = unpack2(acc[p][1]);
            float2 q2 = unpack2(acc[p][2]), q3 = unpack2(acc[p][3]);
            *(float4*)&TPW[rA * 128 + c0] =
                make_float4(q0.x * xA.x, q1.x * xA.y, q2.x * xA.z, q3.x * xA.w);
            *(float4*)&TPW[rB * 128 + c0] =
                make_float4(q0.y * xB.x, q1.y * xB.y, q2.y * xB.z, q3.y * xB.w);
        }
        __syncthreads();

        // scatter: run-length reduce over 64 dst-sorted edges.
        // Interior runs are COMPLETE for their dst (CSR-sorted) -> plain STG.
        // Only first run (may continue from prev tile) and final run (may
        // continue into next tile) need atomics.
        {
            const int d    = 2 * l + 1;
            const int soff = l * l;
            const int ob   = (l == 0) ? 0 : (l == 1) ? 128 : (l == 2) ? 512 : 1152;
            const int ncol = 128 * d;
            for (int q = tid; q < ncol; q += 256) {
                const int c = q / d;
                const int s = q - c * d;
                float a = 0.f;
                int  cur    = Ds[0];
                bool bstart = true;
#pragma unroll 8
                for (int e = 0; e < 64; e++) {
                    int dn = Ds[e];
                    if (dn != cur) {
                        float* p = &out[(size_t)cur * OUTC + ob + q];
                        if (bstart) atomicAdd(p, a); else *p = a;
                        a = 0.f; cur = dn; bstart = false;
                    }
                    a += TPW[e * 128 + c] * SHs[e * 16 + soff + s];
                }
                atomicAdd(&out[(size_t)cur * OUTC + ob + q], a);
            }
        }
        __syncthreads();
    }
}

// ---------------- launch ----------------
extern "C" void kernel_launch(void* const* d_in, const int* in_sizes, int n_in,
                              void* d_out, int out_size)
{
    const float* src_features = (const float*)d_in[0];
    const float* edge_sh      = (const float*)d_in[1];
    const float* edge_emb     = (const float*)d_in[2];
    const float* W1           = (const float*)d_in[3];
    const float* W2           = (const float*)d_in[4];
    const int*   src          = (const int*)d_in[5];
    const int*   dst          = (const int*)d_in[6];
    float*       out          = (float*)d_out;
    (void)in_sizes; (void)n_in; (void)out_size;

    static bool attr_done = false;
    if (!attr_done) {
        cudaFuncSetAttribute(fused_k, cudaFuncAttributeMaxDynamicSharedMemorySize,
                             SMEM_BYTES);
        attr_done = true;
    }

    // CSR build
    zero_cnt_k<<<(NDST + 255) / 256, 256>>>();
    hist_k<<<(E_CNT + 255) / 256, 256>>>(dst);
    scan_k<<<1, 1024>>>();
    fill_k<<<(E_CNT + 255) / 256, 256>>>(dst);

    // zero output (STG-interior + atomic-boundary accumulation target)
    const int n4 = NDST * OUTC / 4;
    zero_out_k<<<(n4 + 255) / 256, 256>>>((float4*)out, n4);

    // fused FFMA2 MLP + TP + scatter (64 edges/block, 2 CTAs/SM)
    const int nblk = (E_CNT + 63) / 64;
    fused_k<<<nblk, 256, SMEM_BYTES>>>(src_features, edge_sh, edge_emb,
                                       W1, W2, src, dst, out);
}

// round 13
// speedup vs baseline: 1.6953x; 1.0656x over previous
#include <cuda_runtime.h>
#include <cstdint>

typedef unsigned long long u64;

#define E_CNT 100000
#define NDST  10000
#define OUTC  2048

// ---------------- small device scratch (CSR only) ----------------
__device__ int g_counts[NDST];
__device__ int g_cursor[NDST];
__device__ int g_eid   [E_CNT];

// ---------------- prologue kernels ----------------
__global__ void zero_cnt_k() {
    int i = blockIdx.x * blockDim.x + threadIdx.x;
    if (i < NDST) g_counts[i] = 0;
}
__global__ void hist_k(const int* __restrict__ dst) {
    int e = blockIdx.x * blockDim.x + threadIdx.x;
    if (e < E_CNT) atomicAdd(&g_counts[dst[e]], 1);
}
__global__ void scan_k() {
    __shared__ int ss[1024];
    const int tid = threadIdx.x;
    const int CH = 10;
    int base = tid * CH, loc[CH], s = 0;
#pragma unroll
    for (int i = 0; i < CH; i++) {
        int idx = base + i;
        int v = (idx < NDST) ? g_counts[idx] : 0;
        loc[i] = s; s += v;
    }
    ss[tid] = s; __syncthreads();
    for (int off = 1; off < 1024; off <<= 1) {
        int v = 0;
        if (tid >= off) v = ss[tid - off];
        __syncthreads();
        if (tid >= off) ss[tid] += v;
        __syncthreads();
    }
    int excl = (tid == 0) ? 0 : ss[tid - 1];
#pragma unroll
    for (int i = 0; i < CH; i++) {
        int idx = base + i;
        if (idx < NDST) g_cursor[idx] = excl + loc[i];
    }
}
__global__ void fill_k(const int* __restrict__ dst) {
    int e = blockIdx.x * blockDim.x + threadIdx.x;
    if (e < E_CNT) {
        int p = atomicAdd(&g_cursor[dst[e]], 1);
        g_eid[p] = e;
    }
}
__global__ void zero_out_k(float4* __restrict__ out, int n4) {
    int i = blockIdx.x * blockDim.x + threadIdx.x;
    if (i < n4) out[i] = make_float4(0.f, 0.f, 0.f, 0.f);
}

// ---------------- packed fp32x2 helpers ----------------
__device__ __forceinline__ void ffma2(u64& d, u64 a, u64 b) {
    asm("fma.rn.f32x2 %0, %1, %2, %0;" : "+l"(d) : "l"(a), "l"(b));
}
__device__ __forceinline__ u64 pack2(float x) {
    u64 r; asm("mov.b64 %0, {%1, %1};" : "=l"(r) : "f"(x)); return r;
}
__device__ __forceinline__ u64 packf2(float lo, float hi) {
    u64 r; asm("mov.b64 %0, {%1, %2};" : "=l"(r) : "f"(lo), "f"(hi)); return r;
}
__device__ __forceinline__ float2 unpack2(u64 v) {
    float2 f; asm("mov.b64 {%0, %1}, %2;" : "=f"(f.x), "=f"(f.y) : "l"(v)); return f;
}
__device__ __forceinline__ float silu_f(float x) {
    return x / (1.f + __expf(-x));
}

// ---------------- smem layout (float offsets; exactly R10) ----------------
// Hst [128][66] | Ws [64][128] (EMBt [64][66] aliases) |
// W1s [64][128] (TPW [64][128] aliases) | SHs [64][16] | ints
#define F_HST  0            // 8448 floats
#define F_WS   8448         // 8192 floats (EMBt aliases: 4224)
#define F_W1S  16640        // 8192 floats (TPW aliases)
#define F_SHS  24832        // 1024 floats
#define F_END  25856
#define SMEM_BYTES ((F_END + 192) * 4)

// ---------------- fused kernel: FFMA2 MLP + TP + segment scatter -----------
__global__ __launch_bounds__(256, 2) void fused_k(
    const float* __restrict__ src_features,
    const float* __restrict__ edge_sh,
    const float* __restrict__ edge_emb,
    const float* __restrict__ W1,
    const float* __restrict__ W2,
    const int*   __restrict__ src,
    const int*   __restrict__ dst,
    float*       __restrict__ out)
{
    extern __shared__ float sm[];
    float* Hst  = sm + F_HST;    // [k=128][row 64+2pad]
    float* Ws   = sm + F_WS;     // [k=64][n 128]
    float* EMBt = Ws;            // [k=64][row 64+2pad] alias
    float* W1s  = sm + F_W1S;    // [k=64][n 128]
    float* TPW  = W1s;           // [row 64][c 128] alias
    float* SHs  = sm + F_SHS;    // [row 64][16]
    int*   Es   = (int*)(sm + F_END);
    int*   Ss   = Es + 64;
    int*   Ds   = Ss + 64;

    const int tid = threadIdx.x;
    const int tr  = tid >> 5;     // warp id 0..7 -> rows tr*8 .. tr*8+7
    const int tc  = tid & 31;     // lane -> cols tc*4 .. tc*4+3
    const int r0  = tr * 8;
    const int c0  = tc * 4;
    const int stg_k = tid >> 5;   // staging row (reused)
    const int stg_f = tid & 31;

    // ---- stage edge metadata (pads replicate last edge; SH pads -> 0) ----
    const int pos0 = blockIdx.x * 64;
    const int nE   = (E_CNT - pos0 < 64) ? (E_CNT - pos0) : 64;
    if (tid < 64) {
        int sl = (tid < nE) ? tid : (nE - 1);
        int e  = g_eid[pos0 + sl];
        Es[tid] = e; Ss[tid] = src[e]; Ds[tid] = dst[e];
    }
    __syncthreads();

    // ---- stage EMBt (transposed, *1/8 folded here), W1s (raw), SHs (*w2s) ----
    const float w2s = 0.08838834764831845f;    // 1/sqrt(128)
#pragma unroll
    for (int it = 0; it < 4; it++) {           // EMB: 64 x 16 float4 -> EMBt[k][row]
        int li = tid + it * 256;
        int slot = li >> 4, f = li & 15;
        float4 v = *(const float4*)&edge_emb[(size_t)Es[slot] * 64 + f * 4];
        EMBt[(f * 4 + 0) * 66 + slot] = v.x * 0.125f;
        EMBt[(f * 4 + 1) * 66 + slot] = v.y * 0.125f;
        EMBt[(f * 4 + 2) * 66 + slot] = v.z * 0.125f;
        EMBt[(f * 4 + 3) * 66 + slot] = v.w * 0.125f;
    }
#pragma unroll
    for (int it = 0; it < 8; it++) {           // W1s[k][n] = W1[k][n] (unscaled)
        int li = tid + it * 256;
        int k = li >> 5, f = li & 31;
        *(float4*)&W1s[k * 128 + f * 4] = *(const float4*)&W1[(size_t)k * 128 + f * 4];
    }
    {                                          // SHs: 64 x 4 float4, *w2s (zero pads)
        int slot = tid >> 2, j = tid & 3;
        float4 v = make_float4(0.f, 0.f, 0.f, 0.f);
        if (slot < nE) {
            v = *(const float4*)&edge_sh[(size_t)Es[slot] * 16 + j * 4];
            v.x *= w2s; v.y *= w2s; v.z *= w2s; v.w *= w2s;
        }
        *(float4*)&SHs[slot * 16 + j * 4] = v;
    }
    __syncthreads();

    // ---- prefetch W2 chunk 0 (l=0, k-half 0) while GEMM1 computes ----
    float4 pf[8];
#pragma unroll
    for (int it = 0; it < 8; it++) {
        int k = stg_k + (it & 1) * 32 + (it >> 1 & 1) * 8 + (it >> 2) * 16; // any cover
        (void)k;
    }
    // simple per-it mapping: li = tid + it*256 -> k = li>>5 in 0..63, f = li&31
#pragma unroll
    for (int it = 0; it < 8; it++) {
        int li = tid + it * 256;
        int k = li >> 5, f = li & 31;
        pf[it] = *(const float4*)&W2[(size_t)k * 512 + f * 4];
    }

    // ---- GEMM1: Hst = silu(EMB @ W1s)^T, 64x128x64, FFMA2 ----
    {
        u64 acc[4][4];   // [row-pair p][col j]: {row r0+2p, row r0+2p+1}
#pragma unroll
        for (int p = 0; p < 4; p++)
#pragma unroll
            for (int j = 0; j < 4; j++) acc[p][j] = 0ull;

#pragma unroll 8
        for (int kk = 0; kk < 64; kk++) {
            float4 rb = *(const float4*)&W1s[kk * 128 + c0];
            u64 bb0 = pack2(rb.x), bb1 = pack2(rb.y);
            u64 bb2 = pack2(rb.z), bb3 = pack2(rb.w);
#pragma unroll
            for (int p = 0; p < 4; p++) {
                u64 ap = *(const u64*)&EMBt[kk * 66 + r0 + 2 * p];  // pair broadcast
                ffma2(acc[p][0], ap, bb0); ffma2(acc[p][1], ap, bb1);
                ffma2(acc[p][2], ap, bb2); ffma2(acc[p][3], ap, bb3);
            }
        }
        // epilogue: silu -> Hst[c][row] (pair store)
#pragma unroll
        for (int p = 0; p < 4; p++)
#pragma unroll
            for (int j = 0; j < 4; j++) {
                float2 v = unpack2(acc[p][j]);
                v.x = silu_f(v.x); v.y = silu_f(v.y);
                *(u64*)&Hst[(c0 + j) * 66 + r0 + 2 * p] = packf2(v.x, v.y);
            }
    }
    __syncthreads();   // Hst ready; EMBt(Ws) and W1s(TPW) free

    // ---- per-l: GEMM2 (FFMA2, W2 reg-prefetch) + fold + segment scatter ----
    for (int l = 0; l < 4; l++) {
        u64 acc[4][4];
#pragma unroll
        for (int p = 0; p < 4; p++)
#pragma unroll
            for (int j = 0; j < 4; j++) acc[p][j] = 0ull;

#pragma unroll
        for (int half = 0; half < 2; half++) {
            // commit prefetched chunk to Ws
#pragma unroll
            for (int it = 0; it < 8; it++) {
                int li = tid + it * 256;
                int k = li >> 5, f = li & 31;
                *(float4*)&Ws[k * 128 + f * 4] = pf[it];
            }
            __syncthreads();

            // prefetch NEXT chunk (clamped; last chunk reloads itself)
            {
                int c = l * 2 + half + 1;
                if (c > 7) c = 7;
                int lc = c >> 1, kc = (c & 1) * 64;
#pragma unroll
                for (int it = 0; it < 8; it++) {
                    int li = tid + it * 256;
                    int k = li >> 5, f = li & 31;
                    pf[it] = *(const float4*)&W2[(size_t)(kc + k) * 512 + lc * 128 + f * 4];
                }
            }

            const int k0 = half * 64;
#pragma unroll 8
            for (int kk = 0; kk < 64; kk++) {
                float4 rb = *(const float4*)&Ws[kk * 128 + c0];
                u64 bb0 = pack2(rb.x), bb1 = pack2(rb.y);
                u64 bb2 = pack2(rb.z), bb3 = pack2(rb.w);
#pragma unroll
                for (int p = 0; p < 4; p++) {
                    u64 ap = *(const u64*)&Hst[(k0 + kk) * 66 + r0 + 2 * p];
                    ffma2(acc[p][0], ap, bb0); ffma2(acc[p][1], ap, bb1);
                    ffma2(acc[p][2], ap, bb2); ffma2(acc[p][3], ap, bb3);
                }
            }
            __syncthreads();   // Ws reads complete before next commit
        }

        // fold: TPW[row][c] = acc * x_src[src[row]][c]
#pragma unroll
        for (int p = 0; p < 4; p++) {
            int rA = r0 + 2 * p, rB = rA + 1;
            float4 xA = *(const float4*)&src_features[(size_t)Ss[rA] * 128 + c0];
            float4 xB = *(const float4*)&src_features[(size_t)Ss[rB] * 128 + c0];
            float2 q0 = unpack2(acc[p][0]), q1 = unpack2(acc[p][1]);
            float2 q2 = unpack2(acc[p][2]), q3 = unpack2(acc[p][3]);
            *(float4*)&TPW[rA * 128 + c0] =
                make_float4(q0.x * xA.x, q1.x * xA.y, q2.x * xA.z, q3.x * xA.w);
            *(float4*)&TPW[rB * 128 + c0] =
                make_float4(q0.y * xB.x, q1.y * xB.y, q2.y * xB.z, q3.y * xB.w);
        }
        __syncthreads();

        // scatter: run-length reduce over 64 dst-sorted edges (R10 form)
        {
            const int d    = 2 * l + 1;
            const int soff = l * l;
            const int ob   = (l == 0) ? 0 : (l == 1) ? 128 : (l == 2) ? 512 : 1152;
            const int ncol = 128 * d;
            for (int q = tid; q < ncol; q += 256) {
                const int c = q / d;
                const int s = q - c * d;
                float a = 0.f;
                int cur = Ds[0];
#pragma unroll 8
                for (int e = 0; e < 64; e++) {
                    int dn = Ds[e];
                    if (dn != cur) {
                        atomicAdd(&out[(size_t)cur * OUTC + ob + q], a);
                        a = 0.f; cur = dn;
                    }
                    a += TPW[e * 128 + c] * SHs[e * 16 + soff + s];
                }
                atomicAdd(&out[(size_t)cur * OUTC + ob + q], a);
            }
        }
        __syncthreads();
    }
}

// ---------------- launch ----------------
extern "C" void kernel_launch(void* const* d_in, const int* in_sizes, int n_in,
                              void* d_out, int out_size)
{
    const float* src_features = (const float*)d_in[0];
    const float* edge_sh      = (const float*)d_in[1];
    const float* edge_emb     = (const float*)d_in[2];
    const float* W1           = (const float*)d_in[3];
    const float* W2           = (const float*)d_in[4];
    const int*   src          = (const int*)d_in[5];
    const int*   dst          = (const int*)d_in[6];
    float*       out          = (float*)d_out;
    (void)in_sizes; (void)n_in; (void)out_size;

    static bool attr_done = false;
    if (!attr_done) {
        cudaFuncSetAttribute(fused_k, cudaFuncAttributeMaxDynamicSharedMemorySize,
                             SMEM_BYTES);
        attr_done = true;
    }

    // CSR build
    zero_cnt_k<<<(NDST + 255) / 256, 256>>>();
    hist_k<<<(E_CNT + 255) / 256, 256>>>(dst);
    scan_k<<<1, 1024>>>();
    fill_k<<<(E_CNT + 255) / 256, 256>>>(dst);

    // zero output (atomic accumulation target)
    const int n4 = NDST * OUTC / 4;
    zero_out_k<<<(n4 + 255) / 256, 256>>>((float4*)out, n4);

    // fused FFMA2 MLP + TP + scatter (64 edges/block, 2 CTAs/SM)
    const int nblk = (E_CNT + 63) / 64;
    fused_k<<<nblk, 256, SMEM_BYTES>>>(src_features, edge_sh, edge_emb,
                                       W1, W2, src, dst, out);
}